// round 14
// baseline (speedup 1.0000x reference)
#include <cuda_runtime.h>
#include <cuda_fp16.h>
#include <cstdint>

#define D      128
#define HH     8
#define RR     6
#define BB     6
#define MAXN   50000
#define NPAD   50048              /* 782 * 64 */
#define KDIM   (RR * D)           /* 768 */
#define NOUT   (3 * D)            /* 384 */
#define MAXE   500000
#define NCHUNK0 25024             /* 391 * 64 : row split for scatter/gemm pipeline */

// ---------------- scratch (static device globals; no allocation) ----------------
__device__ __align__(256) __half g_hh[(size_t)MAXN * D];      // fp16 copy of h
__device__ __align__(256) __half g_Sh[(size_t)NPAD * KDIM];   // fp16 per-(dst,rel) sums; rows >= MAXN stay 0
__device__ __align__(256) __half g_Wth[(size_t)NOUT * KDIM];  // [384][768] K-major W^T fp16
__device__ __align__(256) float g_bias[NOUT];
__device__ __align__(256) __half g_QKVh[(size_t)NPAD * NOUT]; // fp16 relu(S@W + b)
__device__ int g_deg[MAXN];
__device__ int g_rowptr[MAXN + 1];
__device__ int g_cursor[MAXN];
__device__ int g_epack[MAXE];                                 // (src<<3)|rel, sorted by dst

// ---------------- side stream + events (created at static-init, never freed) ----------------
struct SideStream {
    cudaStream_t s;
    cudaEvent_t evFork, evJoin1, evJoin2, evS0, evS1, evG;
    SideStream() {
        cudaStreamCreateWithFlags(&s, cudaStreamNonBlocking);
        cudaEventCreateWithFlags(&evFork, cudaEventDisableTiming);
        cudaEventCreateWithFlags(&evJoin1, cudaEventDisableTiming);
        cudaEventCreateWithFlags(&evJoin2, cudaEventDisableTiming);
        cudaEventCreateWithFlags(&evS0, cudaEventDisableTiming);
        cudaEventCreateWithFlags(&evS1, cudaEventDisableTiming);
        cudaEventCreateWithFlags(&evG, cudaEventDisableTiming);
    }
};
static SideStream g_side;

// ---------------- helpers ----------------
__device__ __forceinline__ uint32_t smem_u32(const void* p) {
    uint32_t a;
    asm("{ .reg .u64 t; cvta.to.shared.u64 t, %1; cvt.u32.u64 %0, t; }" : "=r"(a) : "l"(p));
    return a;
}
__device__ __forceinline__ void ldsm4(uint32_t addr, uint32_t* r) {
    asm volatile("ldmatrix.sync.aligned.m8n8.x4.shared.b16 {%0,%1,%2,%3}, [%4];"
                 : "=r"(r[0]), "=r"(r[1]), "=r"(r[2]), "=r"(r[3]) : "r"(addr));
}
__device__ __forceinline__ void mma_f16(float* c, const uint32_t* a, const uint32_t* b) {
    asm volatile("mma.sync.aligned.m16n8k16.row.col.f32.f16.f16.f32 "
                 "{%0,%1,%2,%3}, {%4,%5,%6,%7}, {%8,%9}, {%0,%1,%2,%3};"
                 : "+f"(c[0]), "+f"(c[1]), "+f"(c[2]), "+f"(c[3])
                 : "r"(a[0]), "r"(a[1]), "r"(a[2]), "r"(a[3]), "r"(b[0]), "r"(b[1]));
}

// ---------------- CSR build ----------------
__global__ void zero_deg() {
    int i = blockIdx.x * blockDim.x + threadIdx.x;
    if (i < MAXN) g_deg[i] = 0;
}
__global__ void hist_deg(const int* __restrict__ dst, int E) {
    int i = blockIdx.x * blockDim.x + threadIdx.x;
    if (i < E) atomicAdd(&g_deg[dst[i]], 1);
}
#define SCAN_T 1024
#define CHUNK  49   /* 1024*49 = 50176 >= MAXN */
__global__ void __launch_bounds__(SCAN_T) scan_deg() {
    __shared__ int sums[SCAN_T];
    int t = threadIdx.x;
    int base = t * CHUNK;
    int s = 0;
#pragma unroll 7
    for (int i = 0; i < CHUNK; i++) {
        int idx = base + i;
        if (idx < MAXN) s += g_deg[idx];
    }
    sums[t] = s;
    __syncthreads();
    for (int off = 1; off < SCAN_T; off <<= 1) {
        int v = (t >= off) ? sums[t - off] : 0;
        __syncthreads();
        if (t >= off) sums[t] += v;
        __syncthreads();
    }
    int excl = (t == 0) ? 0 : sums[t - 1];
#pragma unroll 1
    for (int i = 0; i < CHUNK; i++) {
        int idx = base + i;
        if (idx < MAXN) {
            g_rowptr[idx] = excl;
            g_cursor[idx] = excl;
            excl += g_deg[idx];
        }
    }
    if (t == SCAN_T - 1) g_rowptr[MAXN] = excl;
}
__global__ void place_edges(const int* __restrict__ src, const int* __restrict__ dst,
                            const int* __restrict__ et, int E) {
    int i = blockIdx.x * blockDim.x + threadIdx.x;
    if (i >= E) return;
    int pos = atomicAdd(&g_cursor[dst[i]], 1);
    g_epack[pos] = (src[i] << 3) | et[i];
}

// ---------------- convert h to fp16 ----------------
__global__ void conv_h(const float* __restrict__ h) {
    int i = blockIdx.x * blockDim.x + threadIdx.x;
    if (i >= MAXN * D / 4) return;
    float4 v = __ldg((const float4*)h + i);
    __half2 a = __float22half2_rn(make_float2(v.x, v.y));
    __half2 b = __float22half2_rn(make_float2(v.z, v.w));
    uint2 pk;
    pk.x = *(uint32_t*)&a;
    pk.y = *(uint32_t*)&b;
    ((uint2*)g_hh)[i] = pk;
}

// ---------------- build W^T (fp16) + bias ----------------
__global__ void build_Wt(const float* __restrict__ qb, const float* __restrict__ qc, const float* __restrict__ bq,
                         const float* __restrict__ kb, const float* __restrict__ kc, const float* __restrict__ bk,
                         const float* __restrict__ vb, const float* __restrict__ vc, const float* __restrict__ bv) {
    int idx = blockIdx.x * blockDim.x + threadIdx.x;
    if (idx < NOUT)
        g_bias[idx] = (idx < D) ? bq[idx] : (idx < 2 * D) ? bk[idx - D] : bv[idx - 2 * D];
    if (idx >= NOUT * KDIM) return;
    int o = idx / KDIM;
    int k = idx - o * KDIM;
    int r = k >> 7, i2 = k & 127;
    const float* basis; const float* coef; int oo = o;
    if (o < D)          { basis = qb; coef = qc; }
    else if (o < 2 * D) { basis = kb; coef = kc; oo = o - D; }
    else                { basis = vb; coef = vc; oo = o - 2 * D; }
    float acc = 0.f;
#pragma unroll
    for (int b = 0; b < BB; b++)
        acc += coef[r * BB + b] * basis[(size_t)b * D * D + (size_t)i2 * D + oo];
    g_Wth[idx] = __float2half_rn(acc);
}

// ---------------- scatter via CSR: warp per dst, 4-edge batched gathers, row-chunked ----------------
__global__ void scatter_csr(int d_base, int d_count) {
    int dd = blockIdx.x * (blockDim.x >> 5) + (threadIdx.x >> 5);
    if (dd >= d_count) return;
    int d = d_base + dd;
    int lane = threadIdx.x & 31;
    int e0 = __ldg(g_rowptr + d), e1 = __ldg(g_rowptr + d + 1);
    float4 a0 = {0,0,0,0}, a1 = {0,0,0,0}, a2 = {0,0,0,0},
           a3 = {0,0,0,0}, a4 = {0,0,0,0}, a5 = {0,0,0,0};

#define ACCUM(rel, hv) do { \
        float2 f0 = __half22float2(*(__half2*)&(hv).x); \
        float2 f1 = __half22float2(*(__half2*)&(hv).y); \
        switch (rel) { \
            case 0: a0.x += f0.x; a0.y += f0.y; a0.z += f1.x; a0.w += f1.y; break; \
            case 1: a1.x += f0.x; a1.y += f0.y; a1.z += f1.x; a1.w += f1.y; break; \
            case 2: a2.x += f0.x; a2.y += f0.y; a2.z += f1.x; a2.w += f1.y; break; \
            case 3: a3.x += f0.x; a3.y += f0.y; a3.z += f1.x; a3.w += f1.y; break; \
            case 4: a4.x += f0.x; a4.y += f0.y; a4.z += f1.x; a4.w += f1.y; break; \
            default: a5.x += f0.x; a5.y += f0.y; a5.z += f1.x; a5.w += f1.y; break; \
        } } while (0)

    int e = e0;
#pragma unroll 1
    for (; e + 4 <= e1; e += 4) {
        int p0 = __ldg(g_epack + e);
        int p1 = __ldg(g_epack + e + 1);
        int p2 = __ldg(g_epack + e + 2);
        int p3 = __ldg(g_epack + e + 3);
        uint2 h0 = __ldg((const uint2*)(g_hh + (size_t)(p0 >> 3) * D) + lane);
        uint2 h1 = __ldg((const uint2*)(g_hh + (size_t)(p1 >> 3) * D) + lane);
        uint2 h2 = __ldg((const uint2*)(g_hh + (size_t)(p2 >> 3) * D) + lane);
        uint2 h3 = __ldg((const uint2*)(g_hh + (size_t)(p3 >> 3) * D) + lane);
        ACCUM(p0 & 7, h0);
        ACCUM(p1 & 7, h1);
        ACCUM(p2 & 7, h2);
        ACCUM(p3 & 7, h3);
    }
#pragma unroll 1
    for (; e < e1; e++) {
        int pk = __ldg(g_epack + e);
        uint2 hv = __ldg((const uint2*)(g_hh + (size_t)(pk >> 3) * D) + lane);
        ACCUM(pk & 7, hv);
    }
#undef ACCUM

    uint2* srow = (uint2*)(g_Sh + (size_t)d * KDIM);
#define STORE_REL(idx, a) do { \
        __half2 p0 = __float22half2_rn(make_float2(a.x, a.y)); \
        __half2 p1 = __float22half2_rn(make_float2(a.z, a.w)); \
        uint2 pk2; pk2.x = *(uint32_t*)&p0; pk2.y = *(uint32_t*)&p1; \
        srow[idx * 32 + lane] = pk2; } while (0)
    STORE_REL(0, a0); STORE_REL(1, a1); STORE_REL(2, a2);
    STORE_REL(3, a3); STORE_REL(4, a4); STORE_REL(5, a5);
#undef STORE_REL
}

// ---------------- fp16 mma.sync GEMM: QKVh = relu(S @ W + b) ----------------
// CTA 64x128, 8 warps (2M x 4N, warp 32x32), K-chunk 64, 3-stage, 72KB -> 2 CTAs/SM.
#define KCH        64
#define NKCHUNK    (KDIM / KCH)           /* 12 */
#define ATILEB     (64 * 128)              /* 8192 */
#define BTILEB     (128 * 128)             /* 16384 */
#define STAGEB     (ATILEB + BTILEB)       /* 24576 */
#define NSTAGE     3
#define SMEM_TOTAL (NSTAGE * STAGEB)       /* 73728 */

__device__ __forceinline__ void load_tileA(uint32_t sdst, const __half* __restrict__ g,
                                           int k0, int t) {
#pragma unroll
    for (int i = 0; i < 2; i++) {
        int u = i * 256 + t;
        int row = u >> 3, c = u & 7;
        uint32_t off = (uint32_t)(row * 128 + ((c ^ (row & 7)) * 16));
        const void* src = g + (size_t)row * KDIM + k0 + c * 8;
        asm volatile("cp.async.cg.shared.global [%0], [%1], 16;"
                     :: "r"(sdst + off), "l"(src) : "memory");
    }
}
__device__ __forceinline__ void load_tileB(uint32_t sdst, const __half* __restrict__ g,
                                           int k0, int t) {
#pragma unroll
    for (int i = 0; i < 4; i++) {
        int u = i * 256 + t;
        int row = u >> 3, c = u & 7;
        uint32_t off = (uint32_t)(row * 128 + ((c ^ (row & 7)) * 16));
        const void* src = g + (size_t)row * KDIM + k0 + c * 8;
        asm volatile("cp.async.cg.shared.global [%0], [%1], 16;"
                     :: "r"(sdst + off), "l"(src) : "memory");
    }
}

__global__ void __launch_bounds__(256, 2) gemm_qkv_f16(int bm_base) {
    extern __shared__ char smem[];
    uint32_t sbase = smem_u32(smem);
    int t = threadIdx.x;
    int l = t & 31;
    int w = t >> 5;           // 0..7
    int wm = w & 1;           // M warp 0..1 (32 rows)
    int wn = w >> 1;          // N warp 0..3 (32 cols)
    int bm = bm_base + blockIdx.y * 64;
    int bn = blockIdx.x * 128;

    const __half* A = g_Sh + (size_t)bm * KDIM;
    const __half* B = g_Wth + (size_t)bn * KDIM;

    float acc[2][4][4];
#pragma unroll
    for (int i = 0; i < 2; i++)
#pragma unroll
        for (int j = 0; j < 4; j++)
#pragma unroll
            for (int k = 0; k < 4; k++) acc[i][j][k] = 0.f;

#pragma unroll
    for (int c = 0; c < NSTAGE; c++) {
        uint32_t sb = sbase + c * STAGEB;
        load_tileA(sb,          A, c * KCH, t);
        load_tileB(sb + ATILEB, B, c * KCH, t);
        asm volatile("cp.async.commit_group;" ::: "memory");
    }

#pragma unroll 1
    for (int c = 0; c < NKCHUNK; c++) {
        if (c < NKCHUNK - 2)       asm volatile("cp.async.wait_group 2;" ::: "memory");
        else if (c == NKCHUNK - 2) asm volatile("cp.async.wait_group 1;" ::: "memory");
        else                       asm volatile("cp.async.wait_group 0;" ::: "memory");
        __syncthreads();

        uint32_t sb = sbase + (c % NSTAGE) * STAGEB;
        uint32_t stA = sb;
        uint32_t stB = sb + ATILEB;

#pragma unroll
        for (int kk = 0; kk < 4; kk++) {
            uint32_t af[2][4], bf[4][2];
#pragma unroll
            for (int mt = 0; mt < 2; mt++) {
                uint32_t off = (uint32_t)((wm * 32 + mt * 16 + (l & 15)) * 128 +
                                          (((kk * 2 + (l >> 4)) ^ (l & 7)) * 16));
                ldsm4(stA + off, af[mt]);
            }
#pragma unroll
            for (int np = 0; np < 2; np++) {
                uint32_t off = (uint32_t)((wn * 32 + np * 16 + (l & 7) + ((l >> 4) & 1) * 8) * 128 +
                                          (((kk * 2 + ((l >> 3) & 1)) ^ (l & 7)) * 16));
                uint32_t r[4];
                ldsm4(stB + off, r);
                bf[np * 2][0] = r[0];     bf[np * 2][1] = r[1];
                bf[np * 2 + 1][0] = r[2]; bf[np * 2 + 1][1] = r[3];
            }
#pragma unroll
            for (int mt = 0; mt < 2; mt++)
#pragma unroll
                for (int nt = 0; nt < 4; nt++)
                    mma_f16(acc[mt][nt], af[mt], bf[nt]);
        }
        __syncthreads();
        if (c + NSTAGE < NKCHUNK) {
            int cn = c + NSTAGE;
            load_tileA(sb,          A, cn * KCH, t);
            load_tileB(sb + ATILEB, B, cn * KCH, t);
            asm volatile("cp.async.commit_group;" ::: "memory");
        }
    }

    // epilogue: bias + relu -> fp16 (rows padded to NPAD, no bounds checks)
#pragma unroll
    for (int mt = 0; mt < 2; mt++) {
        int r0 = bm + wm * 32 + mt * 16 + (l >> 2);
#pragma unroll
        for (int nt = 0; nt < 4; nt++) {
            int col = bn + wn * 32 + nt * 8 + 2 * (l & 3);
            float2 bb = *(const float2*)(g_bias + col);
            __half2 o0 = __float22half2_rn(make_float2(fmaxf(acc[mt][nt][0] + bb.x, 0.f),
                                                        fmaxf(acc[mt][nt][1] + bb.y, 0.f)));
            __half2 o1 = __float22half2_rn(make_float2(fmaxf(acc[mt][nt][2] + bb.x, 0.f),
                                                        fmaxf(acc[mt][nt][3] + bb.y, 0.f)));
            *(__half2*)(g_QKVh + (size_t)r0 * NOUT + col) = o0;
            *(__half2*)(g_QKVh + (size_t)(r0 + 8) * NOUT + col) = o1;
        }
    }
}

// ---------------- attention via CSR: warp per dst, 4-edge batched gathers ----------------
__global__ void attn_csr(float* __restrict__ out) {
    int d = blockIdx.x * (blockDim.x >> 5) + (threadIdx.x >> 5);
    if (d >= MAXN) return;
    int lane = threadIdx.x & 31;
    int e0 = __ldg(g_rowptr + d), e1 = __ldg(g_rowptr + d + 1);
    uint2 qp = __ldg((const uint2*)(g_QKVh + (size_t)d * NOUT) + lane);
    float2 q0 = __half22float2(*(__half2*)&qp.x);
    float2 q1 = __half22float2(*(__half2*)&qp.y);
    float4 wv = {0, 0, 0, 0};
    float z = 0.f;

#define EDGE(kp, vp) do { \
        float2 k0 = __half22float2(*(__half2*)&(kp).x); \
        float2 k1 = __half22float2(*(__half2*)&(kp).y); \
        float p = q0.x * k0.x + q0.y * k0.y + q1.x * k1.x + q1.y * k1.y; \
        p += __shfl_xor_sync(0xffffffffu, p, 1); \
        p += __shfl_xor_sync(0xffffffffu, p, 2); \
        float wgt = __expf(fminf(fmaxf(p * 0.25f, -10.f), 10.f)); \
        float2 v0 = __half22float2(*(__half2*)&(vp).x); \
        float2 v1 = __half22float2(*(__half2*)&(vp).y); \
        wv.x += v0.x * wgt; wv.y += v0.y * wgt; \
        wv.z += v1.x * wgt; wv.w += v1.y * wgt; \
        z += wgt; } while (0)

    int e = e0;
#pragma unroll 1
    for (; e + 4 <= e1; e += 4) {
        size_t s0 = (size_t)(__ldg(g_epack + e)     >> 3) * NOUT;
        size_t s1 = (size_t)(__ldg(g_epack + e + 1) >> 3) * NOUT;
        size_t s2 = (size_t)(__ldg(g_epack + e + 2) >> 3) * NOUT;
        size_t s3 = (size_t)(__ldg(g_epack + e + 3) >> 3) * NOUT;
        uint2 k0p = __ldg((const uint2*)(g_QKVh + s0 + D) + lane);
        uint2 v0p = __ldg((const uint2*)(g_QKVh + s0 + 2 * D) + lane);
        uint2 k1p = __ldg((const uint2*)(g_QKVh + s1 + D) + lane);
        uint2 v1p = __ldg((const uint2*)(g_QKVh + s1 + 2 * D) + lane);
        uint2 k2p = __ldg((const uint2*)(g_QKVh + s2 + D) + lane);
        uint2 v2p = __ldg((const uint2*)(g_QKVh + s2 + 2 * D) + lane);
        uint2 k3p = __ldg((const uint2*)(g_QKVh + s3 + D) + lane);
        uint2 v3p = __ldg((const uint2*)(g_QKVh + s3 + 2 * D) + lane);
        EDGE(k0p, v0p);
        EDGE(k1p, v1p);
        EDGE(k2p, v2p);
        EDGE(k3p, v3p);
    }
#pragma unroll 1
    for (; e < e1; e++) {
        size_t s = (size_t)(__ldg(g_epack + e) >> 3) * NOUT;
        uint2 kp = __ldg((const uint2*)(g_QKVh + s + D) + lane);
        uint2 vp = __ldg((const uint2*)(g_QKVh + s + 2 * D) + lane);
        EDGE(kp, vp);
    }
#undef EDGE

    float inv = 1.f / (z + 1e-6f);
    float4 o = {wv.x * inv, wv.y * inv, wv.z * inv, wv.w * inv};
    *((float4*)(out + (size_t)d * D) + lane) = o;
}

extern "C" void kernel_launch(void* const* d_in, const int* in_sizes, int n_in,
                              void* d_out, int out_size) {
    const float* h   = (const float*)d_in[0];
    const int*   src = (const int*)d_in[1];
    const int*   dst = (const int*)d_in[2];
    const int*   et  = (const int*)d_in[3];
    const float* Wq_basis = (const float*)d_in[4];
    const float* Wq_coef  = (const float*)d_in[5];
    const float* bq       = (const float*)d_in[6];
    const float* Wk_basis = (const float*)d_in[7];
    const float* Wk_coef  = (const float*)d_in[8];
    const float* bk       = (const float*)d_in[9];
    const float* Wv_basis = (const float*)d_in[10];
    const float* Wv_coef  = (const float*)d_in[11];
    const float* bv       = (const float*)d_in[12];
    float* out = (float*)d_out;

    int E = in_sizes[1];       // 500000

    static bool attr_set = false;
    if (!attr_set) {
        cudaFuncSetAttribute(gemm_qkv_f16, cudaFuncAttributeMaxDynamicSharedMemorySize, SMEM_TOTAL);
        attr_set = true;
    }

    // Fork: side stream runs conv_h + build_Wt concurrently with the CSR build.
    cudaEventRecord(g_side.evFork, 0);
    cudaStreamWaitEvent(g_side.s, g_side.evFork, 0);

    conv_h<<<(MAXN * D / 4 + 255) / 256, 256, 0, g_side.s>>>(h);
    cudaEventRecord(g_side.evJoin1, g_side.s);     // conv_h done
    build_Wt<<<(NOUT * KDIM + 255) / 256, 256, 0, g_side.s>>>(Wq_basis, Wq_coef, bq,
                                                              Wk_basis, Wk_coef, bk,
                                                              Wv_basis, Wv_coef, bv);
    cudaEventRecord(g_side.evJoin2, g_side.s);     // build_Wt done

    // Main stream: CSR build
    zero_deg<<<(MAXN + 255) / 256, 256>>>();
    hist_deg<<<(E + 255) / 256, 256>>>(dst, E);
    scan_deg<<<1, SCAN_T>>>();
    place_edges<<<(E + 255) / 256, 256>>>(src, dst, et, E);

    // scatter chunk 0 (needs CSR + conv_h)
    cudaStreamWaitEvent(0, g_side.evJoin1, 0);
    scatter_csr<<<(NCHUNK0 * 32 + 255) / 256, 256>>>(0, NCHUNK0);
    cudaEventRecord(g_side.evS0, 0);
    // scatter chunk 1 — runs concurrently with gemm chunk 0 on the side stream
    scatter_csr<<<((MAXN - NCHUNK0) * 32 + 255) / 256, 256>>>(NCHUNK0, MAXN - NCHUNK0);
    cudaEventRecord(g_side.evS1, 0);

    // gemm chunk 0 on side stream (needs scatter0 + build_Wt; J2 ordered on side stream)
    cudaStreamWaitEvent(g_side.s, g_side.evS0, 0);
    {
        dim3 gg(NOUT / 128, NCHUNK0 / 64);
        gemm_qkv_f16<<<gg, 256, SMEM_TOTAL, g_side.s>>>(0);
    }
    // gemm chunk 1 (needs scatter1)
    cudaStreamWaitEvent(g_side.s, g_side.evS1, 0);
    {
        dim3 gg(NOUT / 128, (NPAD - NCHUNK0) / 64);
        gemm_qkv_f16<<<gg, 256, SMEM_TOTAL, g_side.s>>>(NCHUNK0);
    }
    cudaEventRecord(g_side.evG, g_side.s);

    // attn needs the full QKVh
    cudaStreamWaitEvent(0, g_side.evG, 0);
    attn_csr<<<(MAXN * 32 + 255) / 256, 256>>>(out);
}

// round 15
// speedup vs baseline: 1.0090x; 1.0090x over previous
#include <cuda_runtime.h>
#include <cuda_fp16.h>
#include <cstdint>

#define D      128
#define HH     8
#define RR     6
#define BB     6
#define MAXN   50000
#define NPAD   50048              /* 782 * 64 */
#define KDIM   (RR * D)           /* 768 */
#define NOUT   (3 * D)            /* 384 */
#define MAXE   500000

// ---------------- scratch (static device globals; no allocation) ----------------
__device__ __align__(256) __half g_hh[(size_t)MAXN * D];      // fp16 copy of h
__device__ __align__(256) __half g_Sh[(size_t)NPAD * KDIM];   // fp16 per-(dst,rel) sums; rows >= MAXN stay 0
__device__ __align__(256) __half g_Wth[(size_t)NOUT * KDIM];  // [384][768] K-major W^T fp16
__device__ __align__(256) float g_bias[NOUT];
__device__ __align__(256) __half g_QKVh[(size_t)NPAD * NOUT]; // fp16 relu(S@W + b)
__device__ int g_deg[MAXN];
__device__ int g_rowptr[MAXN + 1];
__device__ int g_cursor[MAXN];
__device__ int g_epack[MAXE];                                 // (src<<3)|rel, sorted by dst

// ---------------- side stream + events (created at static-init, never freed) ----------------
struct SideStream {
    cudaStream_t s;
    cudaEvent_t evFork, evJoin1, evJoin2;
    SideStream() {
        cudaStreamCreateWithFlags(&s, cudaStreamNonBlocking);
        cudaEventCreateWithFlags(&evFork, cudaEventDisableTiming);
        cudaEventCreateWithFlags(&evJoin1, cudaEventDisableTiming);
        cudaEventCreateWithFlags(&evJoin2, cudaEventDisableTiming);
    }
};
static SideStream g_side;

// ---------------- helpers ----------------
__device__ __forceinline__ uint32_t smem_u32(const void* p) {
    uint32_t a;
    asm("{ .reg .u64 t; cvta.to.shared.u64 t, %1; cvt.u32.u64 %0, t; }" : "=r"(a) : "l"(p));
    return a;
}
__device__ __forceinline__ void ldsm4(uint32_t addr, uint32_t* r) {
    asm volatile("ldmatrix.sync.aligned.m8n8.x4.shared.b16 {%0,%1,%2,%3}, [%4];"
                 : "=r"(r[0]), "=r"(r[1]), "=r"(r[2]), "=r"(r[3]) : "r"(addr));
}
__device__ __forceinline__ void mma_f16(float* c, const uint32_t* a, const uint32_t* b) {
    asm volatile("mma.sync.aligned.m16n8k16.row.col.f32.f16.f16.f32 "
                 "{%0,%1,%2,%3}, {%4,%5,%6,%7}, {%8,%9}, {%0,%1,%2,%3};"
                 : "+f"(c[0]), "+f"(c[1]), "+f"(c[2]), "+f"(c[3])
                 : "r"(a[0]), "r"(a[1]), "r"(a[2]), "r"(a[3]), "r"(b[0]), "r"(b[1]));
}

// ---------------- CSR build ----------------
__global__ void zero_deg() {
    int i = blockIdx.x * blockDim.x + threadIdx.x;
    if (i < MAXN) g_deg[i] = 0;
}
// 4 edges per thread via int4
__global__ void hist_deg(const int* __restrict__ dst, int E) {
    int i = blockIdx.x * blockDim.x + threadIdx.x;
    int base = i * 4;
    if (base + 4 <= E) {
        int4 d4 = __ldg((const int4*)(dst + base));
        atomicAdd(&g_deg[d4.x], 1);
        atomicAdd(&g_deg[d4.y], 1);
        atomicAdd(&g_deg[d4.z], 1);
        atomicAdd(&g_deg[d4.w], 1);
    } else {
        for (int j = base; j < E; j++) atomicAdd(&g_deg[__ldg(dst + j)], 1);
    }
}
#define SCAN_T 1024
#define CHUNK  49   /* 1024*49 = 50176 >= MAXN */
__global__ void __launch_bounds__(SCAN_T) scan_deg() {
    __shared__ int sums[SCAN_T];
    int t = threadIdx.x;
    int base = t * CHUNK;
    int s = 0;
#pragma unroll 7
    for (int i = 0; i < CHUNK; i++) {
        int idx = base + i;
        if (idx < MAXN) s += g_deg[idx];
    }
    sums[t] = s;
    __syncthreads();
    for (int off = 1; off < SCAN_T; off <<= 1) {
        int v = (t >= off) ? sums[t - off] : 0;
        __syncthreads();
        if (t >= off) sums[t] += v;
        __syncthreads();
    }
    int excl = (t == 0) ? 0 : sums[t - 1];
#pragma unroll 1
    for (int i = 0; i < CHUNK; i++) {
        int idx = base + i;
        if (idx < MAXN) {
            g_rowptr[idx] = excl;
            g_cursor[idx] = excl;
            excl += g_deg[idx];
        }
    }
    if (t == SCAN_T - 1) g_rowptr[MAXN] = excl;
}
// 2 edges per thread via int2
__global__ void place_edges(const int* __restrict__ src, const int* __restrict__ dst,
                            const int* __restrict__ et, int E) {
    int i = blockIdx.x * blockDim.x + threadIdx.x;
    int base = i * 2;
    if (base + 2 <= E) {
        int2 s2 = __ldg((const int2*)(src + base));
        int2 d2 = __ldg((const int2*)(dst + base));
        int2 t2 = __ldg((const int2*)(et + base));
        int p0 = atomicAdd(&g_cursor[d2.x], 1);
        g_epack[p0] = (s2.x << 3) | t2.x;
        int p1 = atomicAdd(&g_cursor[d2.y], 1);
        g_epack[p1] = (s2.y << 3) | t2.y;
    } else if (base < E) {
        int pos = atomicAdd(&g_cursor[__ldg(dst + base)], 1);
        g_epack[pos] = (__ldg(src + base) << 3) | __ldg(et + base);
    }
}

// ---------------- convert h to fp16 ----------------
__global__ void conv_h(const float* __restrict__ h) {
    int i = blockIdx.x * blockDim.x + threadIdx.x;
    if (i >= MAXN * D / 4) return;
    float4 v = __ldg((const float4*)h + i);
    __half2 a = __float22half2_rn(make_float2(v.x, v.y));
    __half2 b = __float22half2_rn(make_float2(v.z, v.w));
    uint2 pk;
    pk.x = *(uint32_t*)&a;
    pk.y = *(uint32_t*)&b;
    ((uint2*)g_hh)[i] = pk;
}

// ---------------- build W^T (fp16) + bias ----------------
__global__ void build_Wt(const float* __restrict__ qb, const float* __restrict__ qc, const float* __restrict__ bq,
                         const float* __restrict__ kb, const float* __restrict__ kc, const float* __restrict__ bk,
                         const float* __restrict__ vb, const float* __restrict__ vc, const float* __restrict__ bv) {
    int idx = blockIdx.x * blockDim.x + threadIdx.x;
    if (idx < NOUT)
        g_bias[idx] = (idx < D) ? bq[idx] : (idx < 2 * D) ? bk[idx - D] : bv[idx - 2 * D];
    if (idx >= NOUT * KDIM) return;
    int o = idx / KDIM;
    int k = idx - o * KDIM;
    int r = k >> 7, i2 = k & 127;
    const float* basis; const float* coef; int oo = o;
    if (o < D)          { basis = qb; coef = qc; }
    else if (o < 2 * D) { basis = kb; coef = kc; oo = o - D; }
    else                { basis = vb; coef = vc; oo = o - 2 * D; }
    float acc = 0.f;
#pragma unroll
    for (int b = 0; b < BB; b++)
        acc += coef[r * BB + b] * basis[(size_t)b * D * D + (size_t)i2 * D + oo];
    g_Wth[idx] = __float2half_rn(acc);
}

// ---------------- scatter via CSR: warp per dst, 4-edge batched gathers ----------------
__global__ void scatter_csr() {
    int d = blockIdx.x * (blockDim.x >> 5) + (threadIdx.x >> 5);
    if (d >= MAXN) return;
    int lane = threadIdx.x & 31;
    int e0 = __ldg(g_rowptr + d), e1 = __ldg(g_rowptr + d + 1);
    float4 a0 = {0,0,0,0}, a1 = {0,0,0,0}, a2 = {0,0,0,0},
           a3 = {0,0,0,0}, a4 = {0,0,0,0}, a5 = {0,0,0,0};

#define ACCUM(rel, hv) do { \
        float2 f0 = __half22float2(*(__half2*)&(hv).x); \
        float2 f1 = __half22float2(*(__half2*)&(hv).y); \
        switch (rel) { \
            case 0: a0.x += f0.x; a0.y += f0.y; a0.z += f1.x; a0.w += f1.y; break; \
            case 1: a1.x += f0.x; a1.y += f0.y; a1.z += f1.x; a1.w += f1.y; break; \
            case 2: a2.x += f0.x; a2.y += f0.y; a2.z += f1.x; a2.w += f1.y; break; \
            case 3: a3.x += f0.x; a3.y += f0.y; a3.z += f1.x; a3.w += f1.y; break; \
            case 4: a4.x += f0.x; a4.y += f0.y; a4.z += f1.x; a4.w += f1.y; break; \
            default: a5.x += f0.x; a5.y += f0.y; a5.z += f1.x; a5.w += f1.y; break; \
        } } while (0)

    int e = e0;
#pragma unroll 1
    for (; e + 4 <= e1; e += 4) {
        int p0 = __ldg(g_epack + e);
        int p1 = __ldg(g_epack + e + 1);
        int p2 = __ldg(g_epack + e + 2);
        int p3 = __ldg(g_epack + e + 3);
        uint2 h0 = __ldg((const uint2*)(g_hh + (size_t)(p0 >> 3) * D) + lane);
        uint2 h1 = __ldg((const uint2*)(g_hh + (size_t)(p1 >> 3) * D) + lane);
        uint2 h2 = __ldg((const uint2*)(g_hh + (size_t)(p2 >> 3) * D) + lane);
        uint2 h3 = __ldg((const uint2*)(g_hh + (size_t)(p3 >> 3) * D) + lane);
        ACCUM(p0 & 7, h0);
        ACCUM(p1 & 7, h1);
        ACCUM(p2 & 7, h2);
        ACCUM(p3 & 7, h3);
    }
#pragma unroll 1
    for (; e < e1; e++) {
        int pk = __ldg(g_epack + e);
        uint2 hv = __ldg((const uint2*)(g_hh + (size_t)(pk >> 3) * D) + lane);
        ACCUM(pk & 7, hv);
    }
#undef ACCUM

    uint2* srow = (uint2*)(g_Sh + (size_t)d * KDIM);
#define STORE_REL(idx, a) do { \
        __half2 p0 = __float22half2_rn(make_float2(a.x, a.y)); \
        __half2 p1 = __float22half2_rn(make_float2(a.z, a.w)); \
        uint2 pk2; pk2.x = *(uint32_t*)&p0; pk2.y = *(uint32_t*)&p1; \
        srow[idx * 32 + lane] = pk2; } while (0)
    STORE_REL(0, a0); STORE_REL(1, a1); STORE_REL(2, a2);
    STORE_REL(3, a3); STORE_REL(4, a4); STORE_REL(5, a5);
#undef STORE_REL
}

// ---------------- fp16 mma.sync GEMM: QKVh = relu(S @ W + b) ----------------
// CTA 64x128, 8 warps (2M x 4N, warp 32x32), K-chunk 64, 3-stage, 72KB -> 2 CTAs/SM.
#define KCH        64
#define NKCHUNK    (KDIM / KCH)           /* 12 */
#define ATILEB     (64 * 128)              /* 8192 */
#define BTILEB     (128 * 128)             /* 16384 */
#define STAGEB     (ATILEB + BTILEB)       /* 24576 */
#define NSTAGE     3
#define SMEM_TOTAL (NSTAGE * STAGEB)       /* 73728 */

__device__ __forceinline__ void load_tileA(uint32_t sdst, const __half* __restrict__ g,
                                           int k0, int t) {
#pragma unroll
    for (int i = 0; i < 2; i++) {
        int u = i * 256 + t;
        int row = u >> 3, c = u & 7;
        uint32_t off = (uint32_t)(row * 128 + ((c ^ (row & 7)) * 16));
        const void* src = g + (size_t)row * KDIM + k0 + c * 8;
        asm volatile("cp.async.cg.shared.global [%0], [%1], 16;"
                     :: "r"(sdst + off), "l"(src) : "memory");
    }
}
__device__ __forceinline__ void load_tileB(uint32_t sdst, const __half* __restrict__ g,
                                           int k0, int t) {
#pragma unroll
    for (int i = 0; i < 4; i++) {
        int u = i * 256 + t;
        int row = u >> 3, c = u & 7;
        uint32_t off = (uint32_t)(row * 128 + ((c ^ (row & 7)) * 16));
        const void* src = g + (size_t)row * KDIM + k0 + c * 8;
        asm volatile("cp.async.cg.shared.global [%0], [%1], 16;"
                     :: "r"(sdst + off), "l"(src) : "memory");
    }
}

__global__ void __launch_bounds__(256, 2) gemm_qkv_f16() {
    extern __shared__ char smem[];
    uint32_t sbase = smem_u32(smem);
    int t = threadIdx.x;
    int l = t & 31;
    int w = t >> 5;           // 0..7
    int wm = w & 1;           // M warp 0..1 (32 rows)
    int wn = w >> 1;          // N warp 0..3 (32 cols)
    int bm = blockIdx.y * 64;
    int bn = blockIdx.x * 128;

    const __half* A = g_Sh + (size_t)bm * KDIM;
    const __half* B = g_Wth + (size_t)bn * KDIM;

    float acc[2][4][4];
#pragma unroll
    for (int i = 0; i < 2; i++)
#pragma unroll
        for (int j = 0; j < 4; j++)
#pragma unroll
            for (int k = 0; k < 4; k++) acc[i][j][k] = 0.f;

#pragma unroll
    for (int c = 0; c < NSTAGE; c++) {
        uint32_t sb = sbase + c * STAGEB;
        load_tileA(sb,          A, c * KCH, t);
        load_tileB(sb + ATILEB, B, c * KCH, t);
        asm volatile("cp.async.commit_group;" ::: "memory");
    }

#pragma unroll 1
    for (int c = 0; c < NKCHUNK; c++) {
        if (c < NKCHUNK - 2)       asm volatile("cp.async.wait_group 2;" ::: "memory");
        else if (c == NKCHUNK - 2) asm volatile("cp.async.wait_group 1;" ::: "memory");
        else                       asm volatile("cp.async.wait_group 0;" ::: "memory");
        __syncthreads();

        uint32_t sb = sbase + (c % NSTAGE) * STAGEB;
        uint32_t stA = sb;
        uint32_t stB = sb + ATILEB;

#pragma unroll
        for (int kk = 0; kk < 4; kk++) {
            uint32_t af[2][4], bf[4][2];
#pragma unroll
            for (int mt = 0; mt < 2; mt++) {
                uint32_t off = (uint32_t)((wm * 32 + mt * 16 + (l & 15)) * 128 +
                                          (((kk * 2 + (l >> 4)) ^ (l & 7)) * 16));
                ldsm4(stA + off, af[mt]);
            }
#pragma unroll
            for (int np = 0; np < 2; np++) {
                uint32_t off = (uint32_t)((wn * 32 + np * 16 + (l & 7) + ((l >> 4) & 1) * 8) * 128 +
                                          (((kk * 2 + ((l >> 3) & 1)) ^ (l & 7)) * 16));
                uint32_t r[4];
                ldsm4(stB + off, r);
                bf[np * 2][0] = r[0];     bf[np * 2][1] = r[1];
                bf[np * 2 + 1][0] = r[2]; bf[np * 2 + 1][1] = r[3];
            }
#pragma unroll
            for (int mt = 0; mt < 2; mt++)
#pragma unroll
                for (int nt = 0; nt < 4; nt++)
                    mma_f16(acc[mt][nt], af[mt], bf[nt]);
        }
        __syncthreads();
        if (c + NSTAGE < NKCHUNK) {
            int cn = c + NSTAGE;
            load_tileA(sb,          A, cn * KCH, t);
            load_tileB(sb + ATILEB, B, cn * KCH, t);
            asm volatile("cp.async.commit_group;" ::: "memory");
        }
    }

    // epilogue: bias + relu -> fp16 (rows padded to NPAD, no bounds checks)
#pragma unroll
    for (int mt = 0; mt < 2; mt++) {
        int r0 = bm + wm * 32 + mt * 16 + (l >> 2);
#pragma unroll
        for (int nt = 0; nt < 4; nt++) {
            int col = bn + wn * 32 + nt * 8 + 2 * (l & 3);
            float2 bb = *(const float2*)(g_bias + col);
            __half2 o0 = __float22half2_rn(make_float2(fmaxf(acc[mt][nt][0] + bb.x, 0.f),
                                                        fmaxf(acc[mt][nt][1] + bb.y, 0.f)));
            __half2 o1 = __float22half2_rn(make_float2(fmaxf(acc[mt][nt][2] + bb.x, 0.f),
                                                        fmaxf(acc[mt][nt][3] + bb.y, 0.f)));
            *(__half2*)(g_QKVh + (size_t)r0 * NOUT + col) = o0;
            *(__half2*)(g_QKVh + (size_t)(r0 + 8) * NOUT + col) = o1;
        }
    }
}

// ---------------- attention via CSR: warp per dst, 4-edge batched gathers ----------------
__global__ void attn_csr(float* __restrict__ out) {
    int d = blockIdx.x * (blockDim.x >> 5) + (threadIdx.x >> 5);
    if (d >= MAXN) return;
    int lane = threadIdx.x & 31;
    int e0 = __ldg(g_rowptr + d), e1 = __ldg(g_rowptr + d + 1);
    uint2 qp = __ldg((const uint2*)(g_QKVh + (size_t)d * NOUT) + lane);
    float2 q0 = __half22float2(*(__half2*)&qp.x);
    float2 q1 = __half22float2(*(__half2*)&qp.y);
    float4 wv = {0, 0, 0, 0};
    float z = 0.f;

#define EDGE(kp, vp) do { \
        float2 k0 = __half22float2(*(__half2*)&(kp).x); \
        float2 k1 = __half22float2(*(__half2*)&(kp).y); \
        float p = q0.x * k0.x + q0.y * k0.y + q1.x * k1.x + q1.y * k1.y; \
        p += __shfl_xor_sync(0xffffffffu, p, 1); \
        p += __shfl_xor_sync(0xffffffffu, p, 2); \
        float wgt = __expf(fminf(fmaxf(p * 0.25f, -10.f), 10.f)); \
        float2 v0 = __half22float2(*(__half2*)&(vp).x); \
        float2 v1 = __half22float2(*(__half2*)&(vp).y); \
        wv.x += v0.x * wgt; wv.y += v0.y * wgt; \
        wv.z += v1.x * wgt; wv.w += v1.y * wgt; \
        z += wgt; } while (0)

    int e = e0;
#pragma unroll 1
    for (; e + 4 <= e1; e += 4) {
        size_t s0 = (size_t)(__ldg(g_epack + e)     >> 3) * NOUT;
        size_t s1 = (size_t)(__ldg(g_epack + e + 1) >> 3) * NOUT;
        size_t s2 = (size_t)(__ldg(g_epack + e + 2) >> 3) * NOUT;
        size_t s3 = (size_t)(__ldg(g_epack + e + 3) >> 3) * NOUT;
        uint2 k0p = __ldg((const uint2*)(g_QKVh + s0 + D) + lane);
        uint2 v0p = __ldg((const uint2*)(g_QKVh + s0 + 2 * D) + lane);
        uint2 k1p = __ldg((const uint2*)(g_QKVh + s1 + D) + lane);
        uint2 v1p = __ldg((const uint2*)(g_QKVh + s1 + 2 * D) + lane);
        uint2 k2p = __ldg((const uint2*)(g_QKVh + s2 + D) + lane);
        uint2 v2p = __ldg((const uint2*)(g_QKVh + s2 + 2 * D) + lane);
        uint2 k3p = __ldg((const uint2*)(g_QKVh + s3 + D) + lane);
        uint2 v3p = __ldg((const uint2*)(g_QKVh + s3 + 2 * D) + lane);
        EDGE(k0p, v0p);
        EDGE(k1p, v1p);
        EDGE(k2p, v2p);
        EDGE(k3p, v3p);
    }
#pragma unroll 1
    for (; e < e1; e++) {
        size_t s = (size_t)(__ldg(g_epack + e) >> 3) * NOUT;
        uint2 kp = __ldg((const uint2*)(g_QKVh + s + D) + lane);
        uint2 vp = __ldg((const uint2*)(g_QKVh + s + 2 * D) + lane);
        EDGE(kp, vp);
    }
#undef EDGE

    float inv = 1.f / (z + 1e-6f);
    float4 o = {wv.x * inv, wv.y * inv, wv.z * inv, wv.w * inv};
    *((float4*)(out + (size_t)d * D) + lane) = o;
}

extern "C" void kernel_launch(void* const* d_in, const int* in_sizes, int n_in,
                              void* d_out, int out_size) {
    const float* h   = (const float*)d_in[0];
    const int*   src = (const int*)d_in[1];
    const int*   dst = (const int*)d_in[2];
    const int*   et  = (const int*)d_in[3];
    const float* Wq_basis = (const float*)d_in[4];
    const float* Wq_coef  = (const float*)d_in[5];
    const float* bq       = (const float*)d_in[6];
    const float* Wk_basis = (const float*)d_in[7];
    const float* Wk_coef  = (const float*)d_in[8];
    const float* bk       = (const float*)d_in[9];
    const float* Wv_basis = (const float*)d_in[10];
    const float* Wv_coef  = (const float*)d_in[11];
    const float* bv       = (const float*)d_in[12];
    float* out = (float*)d_out;

    int E = in_sizes[1];       // 500000

    static bool attr_set = false;
    if (!attr_set) {
        cudaFuncSetAttribute(gemm_qkv_f16, cudaFuncAttributeMaxDynamicSharedMemorySize, SMEM_TOTAL);
        attr_set = true;
    }

    // Fork: side stream runs conv_h + build_Wt concurrently with the CSR build.
    cudaEventRecord(g_side.evFork, 0);
    cudaStreamWaitEvent(g_side.s, g_side.evFork, 0);

    conv_h<<<(MAXN * D / 4 + 255) / 256, 256, 0, g_side.s>>>(h);
    cudaEventRecord(g_side.evJoin1, g_side.s);     // conv_h done
    build_Wt<<<(NOUT * KDIM + 255) / 256, 256, 0, g_side.s>>>(Wq_basis, Wq_coef, bq,
                                                              Wk_basis, Wk_coef, bk,
                                                              Wv_basis, Wv_coef, bv);
    cudaEventRecord(g_side.evJoin2, g_side.s);     // build_Wt done

    // Main stream: CSR build
    zero_deg<<<(MAXN + 255) / 256, 256>>>();
    {
        int th = (E + 3) / 4;
        hist_deg<<<(th + 255) / 256, 256>>>(dst, E);
    }
    scan_deg<<<1, SCAN_T>>>();
    {
        int th = (E + 1) / 2;
        place_edges<<<(th + 255) / 256, 256>>>(src, dst, et, E);
    }

    // scatter needs CSR + conv_h
    cudaStreamWaitEvent(0, g_side.evJoin1, 0);
    scatter_csr<<<(MAXN * 32 + 255) / 256, 256>>>();

    // gemm needs scatter + build_Wt
    cudaStreamWaitEvent(0, g_side.evJoin2, 0);
    {
        dim3 gg(NOUT / 128, NPAD / 64);
        gemm_qkv_f16<<<gg, 256, SMEM_TOTAL>>>();
    }

    attn_csr<<<(MAXN * 32 + 255) / 256, 256>>>(out);
}

// round 16
// speedup vs baseline: 1.0231x; 1.0140x over previous
#include <cuda_runtime.h>
#include <cuda_fp16.h>
#include <cstdint>

#define D      128
#define HH     8
#define RR     6
#define BB     6
#define MAXN   50000
#define NPAD   50048              /* 782 * 64 */
#define KDIM   (RR * D)           /* 768 */
#define NOUT   (3 * D)            /* 384 */
#define MAXE   500000

// ---------------- scratch (static device globals; no allocation) ----------------
__device__ __align__(256) __half g_hh[(size_t)MAXN * D];      // fp16 copy of h
__device__ __align__(256) __half g_Sh[(size_t)NPAD * KDIM];   // fp16 per-(dst,rel) sums; rows >= MAXN stay 0
__device__ __align__(256) __half g_Wth[(size_t)NOUT * KDIM];  // [384][768] K-major W^T fp16
__device__ __align__(256) float g_bias[NOUT];
__device__ __align__(256) __half g_QKVh[(size_t)NPAD * NOUT]; // fp16 relu(S@W + b)
__device__ int g_deg[MAXN];
__device__ int g_rowptr[MAXN + 1];
__device__ int g_cursor[MAXN];
__device__ int g_epack[MAXE];                                 // (src<<3)|rel, sorted by dst

// ---------------- side stream + events (created at static-init, never freed) ----------------
struct SideStream {
    cudaStream_t s;
    cudaEvent_t evFork, evJoin1, evJoin2;
    SideStream() {
        cudaStreamCreateWithFlags(&s, cudaStreamNonBlocking);
        cudaEventCreateWithFlags(&evFork, cudaEventDisableTiming);
        cudaEventCreateWithFlags(&evJoin1, cudaEventDisableTiming);
        cudaEventCreateWithFlags(&evJoin2, cudaEventDisableTiming);
    }
};
static SideStream g_side;

// ---------------- helpers ----------------
__device__ __forceinline__ uint32_t smem_u32(const void* p) {
    uint32_t a;
    asm("{ .reg .u64 t; cvta.to.shared.u64 t, %1; cvt.u32.u64 %0, t; }" : "=r"(a) : "l"(p));
    return a;
}
__device__ __forceinline__ void ldsm4(uint32_t addr, uint32_t* r) {
    asm volatile("ldmatrix.sync.aligned.m8n8.x4.shared.b16 {%0,%1,%2,%3}, [%4];"
                 : "=r"(r[0]), "=r"(r[1]), "=r"(r[2]), "=r"(r[3]) : "r"(addr));
}
__device__ __forceinline__ void mma_f16(float* c, const uint32_t* a, const uint32_t* b) {
    asm volatile("mma.sync.aligned.m16n8k16.row.col.f32.f16.f16.f32 "
                 "{%0,%1,%2,%3}, {%4,%5,%6,%7}, {%8,%9}, {%0,%1,%2,%3};"
                 : "+f"(c[0]), "+f"(c[1]), "+f"(c[2]), "+f"(c[3])
                 : "r"(a[0]), "r"(a[1]), "r"(a[2]), "r"(a[3]), "r"(b[0]), "r"(b[1]));
}

// ---------------- CSR build ----------------
__global__ void zero_deg() {
    int i = blockIdx.x * blockDim.x + threadIdx.x;
    if (i < MAXN) g_deg[i] = 0;
}
// 4 edges per thread via int4
__global__ void hist_deg(const int* __restrict__ dst, int E) {
    int i = blockIdx.x * blockDim.x + threadIdx.x;
    int base = i * 4;
    if (base + 4 <= E) {
        int4 d4 = __ldg((const int4*)(dst + base));
        atomicAdd(&g_deg[d4.x], 1);
        atomicAdd(&g_deg[d4.y], 1);
        atomicAdd(&g_deg[d4.z], 1);
        atomicAdd(&g_deg[d4.w], 1);
    } else {
        for (int j = base; j < E; j++) atomicAdd(&g_deg[__ldg(dst + j)], 1);
    }
}
#define SCAN_T 1024
#define CHUNK  49   /* 1024*49 = 50176 >= MAXN */
__global__ void __launch_bounds__(SCAN_T) scan_deg() {
    __shared__ int sums[SCAN_T];
    int t = threadIdx.x;
    int base = t * CHUNK;
    int s = 0;
#pragma unroll 7
    for (int i = 0; i < CHUNK; i++) {
        int idx = base + i;
        if (idx < MAXN) s += g_deg[idx];
    }
    sums[t] = s;
    __syncthreads();
    for (int off = 1; off < SCAN_T; off <<= 1) {
        int v = (t >= off) ? sums[t - off] : 0;
        __syncthreads();
        if (t >= off) sums[t] += v;
        __syncthreads();
    }
    int excl = (t == 0) ? 0 : sums[t - 1];
#pragma unroll 1
    for (int i = 0; i < CHUNK; i++) {
        int idx = base + i;
        if (idx < MAXN) {
            g_rowptr[idx] = excl;
            g_cursor[idx] = excl;
            excl += g_deg[idx];
        }
    }
    if (t == SCAN_T - 1) g_rowptr[MAXN] = excl;
}
// 2 edges per thread via int2
__global__ void place_edges(const int* __restrict__ src, const int* __restrict__ dst,
                            const int* __restrict__ et, int E) {
    int i = blockIdx.x * blockDim.x + threadIdx.x;
    int base = i * 2;
    if (base + 2 <= E) {
        int2 s2 = __ldg((const int2*)(src + base));
        int2 d2 = __ldg((const int2*)(dst + base));
        int2 t2 = __ldg((const int2*)(et + base));
        int p0 = atomicAdd(&g_cursor[d2.x], 1);
        g_epack[p0] = (s2.x << 3) | t2.x;
        int p1 = atomicAdd(&g_cursor[d2.y], 1);
        g_epack[p1] = (s2.y << 3) | t2.y;
    } else if (base < E) {
        int pos = atomicAdd(&g_cursor[__ldg(dst + base)], 1);
        g_epack[pos] = (__ldg(src + base) << 3) | __ldg(et + base);
    }
}

// ---------------- convert h to fp16 ----------------
__global__ void conv_h(const float* __restrict__ h) {
    int i = blockIdx.x * blockDim.x + threadIdx.x;
    if (i >= MAXN * D / 4) return;
    float4 v = __ldg((const float4*)h + i);
    __half2 a = __float22half2_rn(make_float2(v.x, v.y));
    __half2 b = __float22half2_rn(make_float2(v.z, v.w));
    uint2 pk;
    pk.x = *(uint32_t*)&a;
    pk.y = *(uint32_t*)&b;
    ((uint2*)g_hh)[i] = pk;
}

// ---------------- build W^T (fp16) + bias ----------------
__global__ void build_Wt(const float* __restrict__ qb, const float* __restrict__ qc, const float* __restrict__ bq,
                         const float* __restrict__ kb, const float* __restrict__ kc, const float* __restrict__ bk,
                         const float* __restrict__ vb, const float* __restrict__ vc, const float* __restrict__ bv) {
    int idx = blockIdx.x * blockDim.x + threadIdx.x;
    if (idx < NOUT)
        g_bias[idx] = (idx < D) ? bq[idx] : (idx < 2 * D) ? bk[idx - D] : bv[idx - 2 * D];
    if (idx >= NOUT * KDIM) return;
    int o = idx / KDIM;
    int k = idx - o * KDIM;
    int r = k >> 7, i2 = k & 127;
    const float* basis; const float* coef; int oo = o;
    if (o < D)          { basis = qb; coef = qc; }
    else if (o < 2 * D) { basis = kb; coef = kc; oo = o - D; }
    else                { basis = vb; coef = vc; oo = o - 2 * D; }
    float acc = 0.f;
#pragma unroll
    for (int b = 0; b < BB; b++)
        acc += coef[r * BB + b] * basis[(size_t)b * D * D + (size_t)i2 * D + oo];
    g_Wth[idx] = __float2half_rn(acc);
}

// ---------------- scatter via CSR: warp per dst, 4-edge batched gathers ----------------
__global__ void scatter_csr() {
    int d = blockIdx.x * (blockDim.x >> 5) + (threadIdx.x >> 5);
    if (d >= MAXN) return;
    int lane = threadIdx.x & 31;
    int e0 = __ldg(g_rowptr + d), e1 = __ldg(g_rowptr + d + 1);
    float4 a0 = {0,0,0,0}, a1 = {0,0,0,0}, a2 = {0,0,0,0},
           a3 = {0,0,0,0}, a4 = {0,0,0,0}, a5 = {0,0,0,0};

#define ACCUM(rel, hv) do { \
        float2 f0 = __half22float2(*(__half2*)&(hv).x); \
        float2 f1 = __half22float2(*(__half2*)&(hv).y); \
        switch (rel) { \
            case 0: a0.x += f0.x; a0.y += f0.y; a0.z += f1.x; a0.w += f1.y; break; \
            case 1: a1.x += f0.x; a1.y += f0.y; a1.z += f1.x; a1.w += f1.y; break; \
            case 2: a2.x += f0.x; a2.y += f0.y; a2.z += f1.x; a2.w += f1.y; break; \
            case 3: a3.x += f0.x; a3.y += f0.y; a3.z += f1.x; a3.w += f1.y; break; \
            case 4: a4.x += f0.x; a4.y += f0.y; a4.z += f1.x; a4.w += f1.y; break; \
            default: a5.x += f0.x; a5.y += f0.y; a5.z += f1.x; a5.w += f1.y; break; \
        } } while (0)

    int e = e0;
#pragma unroll 1
    for (; e + 4 <= e1; e += 4) {
        int p0 = __ldg(g_epack + e);
        int p1 = __ldg(g_epack + e + 1);
        int p2 = __ldg(g_epack + e + 2);
        int p3 = __ldg(g_epack + e + 3);
        uint2 h0 = __ldg((const uint2*)(g_hh + (size_t)(p0 >> 3) * D) + lane);
        uint2 h1 = __ldg((const uint2*)(g_hh + (size_t)(p1 >> 3) * D) + lane);
        uint2 h2 = __ldg((const uint2*)(g_hh + (size_t)(p2 >> 3) * D) + lane);
        uint2 h3 = __ldg((const uint2*)(g_hh + (size_t)(p3 >> 3) * D) + lane);
        ACCUM(p0 & 7, h0);
        ACCUM(p1 & 7, h1);
        ACCUM(p2 & 7, h2);
        ACCUM(p3 & 7, h3);
    }
#pragma unroll 1
    for (; e < e1; e++) {
        int pk = __ldg(g_epack + e);
        uint2 hv = __ldg((const uint2*)(g_hh + (size_t)(pk >> 3) * D) + lane);
        ACCUM(pk & 7, hv);
    }
#undef ACCUM

    uint2* srow = (uint2*)(g_Sh + (size_t)d * KDIM);
#define STORE_REL(idx, a) do { \
        __half2 p0 = __float22half2_rn(make_float2(a.x, a.y)); \
        __half2 p1 = __float22half2_rn(make_float2(a.z, a.w)); \
        uint2 pk2; pk2.x = *(uint32_t*)&p0; pk2.y = *(uint32_t*)&p1; \
        srow[idx * 32 + lane] = pk2; } while (0)
    STORE_REL(0, a0); STORE_REL(1, a1); STORE_REL(2, a2);
    STORE_REL(3, a3); STORE_REL(4, a4); STORE_REL(5, a5);
#undef STORE_REL
}

// ---------------- fp16 mma.sync GEMM: QKVh = relu(S @ W + b) ----------------
// CTA 64x128, 8 warps (2M x 4N, warp 32x32), K-chunk 64, 3-stage cp.async,
// canonical multistage: prologue 2 chunks, ONE sync per chunk, prefetch BEFORE compute.
#define KCH        64
#define NKCHUNK    (KDIM / KCH)           /* 12 */
#define ATILEB     (64 * 128)              /* 8192 */
#define BTILEB     (128 * 128)             /* 16384 */
#define STAGEB     (ATILEB + BTILEB)       /* 24576 */
#define NSTAGE     3
#define SMEM_TOTAL (NSTAGE * STAGEB)       /* 73728 */

__device__ __forceinline__ void load_tileA(uint32_t sdst, const __half* __restrict__ g,
                                           int k0, int t) {
#pragma unroll
    for (int i = 0; i < 2; i++) {
        int u = i * 256 + t;
        int row = u >> 3, c = u & 7;
        uint32_t off = (uint32_t)(row * 128 + ((c ^ (row & 7)) * 16));
        const void* src = g + (size_t)row * KDIM + k0 + c * 8;
        asm volatile("cp.async.cg.shared.global [%0], [%1], 16;"
                     :: "r"(sdst + off), "l"(src) : "memory");
    }
}
__device__ __forceinline__ void load_tileB(uint32_t sdst, const __half* __restrict__ g,
                                           int k0, int t) {
#pragma unroll
    for (int i = 0; i < 4; i++) {
        int u = i * 256 + t;
        int row = u >> 3, c = u & 7;
        uint32_t off = (uint32_t)(row * 128 + ((c ^ (row & 7)) * 16));
        const void* src = g + (size_t)row * KDIM + k0 + c * 8;
        asm volatile("cp.async.cg.shared.global [%0], [%1], 16;"
                     :: "r"(sdst + off), "l"(src) : "memory");
    }
}

__global__ void __launch_bounds__(256, 2) gemm_qkv_f16() {
    extern __shared__ char smem[];
    uint32_t sbase = smem_u32(smem);
    int t = threadIdx.x;
    int l = t & 31;
    int w = t >> 5;           // 0..7
    int wm = w & 1;           // M warp 0..1 (32 rows)
    int wn = w >> 1;          // N warp 0..3 (32 cols)
    int bm = blockIdx.y * 64;
    int bn = blockIdx.x * 128;

    const __half* A = g_Sh + (size_t)bm * KDIM;
    const __half* B = g_Wth + (size_t)bn * KDIM;

    float acc[2][4][4];
#pragma unroll
    for (int i = 0; i < 2; i++)
#pragma unroll
        for (int j = 0; j < 4; j++)
#pragma unroll
            for (int k = 0; k < 4; k++) acc[i][j][k] = 0.f;

    // prologue: chunks 0,1 into stages 0,1 (2 groups in flight)
#pragma unroll
    for (int c = 0; c < 2; c++) {
        uint32_t sb = sbase + c * STAGEB;
        load_tileA(sb,          A, c * KCH, t);
        load_tileB(sb + ATILEB, B, c * KCH, t);
        asm volatile("cp.async.commit_group;" ::: "memory");
    }

#pragma unroll 1
    for (int c = 0; c < NKCHUNK; c++) {
        // chunk c must be resident; keep 1 group in flight except at the tail
        if (c == NKCHUNK - 1) asm volatile("cp.async.wait_group 0;" ::: "memory");
        else                  asm volatile("cp.async.wait_group 1;" ::: "memory");
        // single barrier: makes chunk c visible AND guarantees everyone is done
        // reading stage (c+2)%3 (which held chunk c-1, consumed last iteration)
        __syncthreads();

        // prefetch chunk c+2 into stage (c+2)%3 BEFORE compute (hidden under mma)
        if (c + 2 < NKCHUNK) {
            int cn = c + 2;
            uint32_t sbn = sbase + (cn % NSTAGE) * STAGEB;
            load_tileA(sbn,          A, cn * KCH, t);
            load_tileB(sbn + ATILEB, B, cn * KCH, t);
            asm volatile("cp.async.commit_group;" ::: "memory");
        }

        uint32_t sb = sbase + (c % NSTAGE) * STAGEB;
        uint32_t stA = sb;
        uint32_t stB = sb + ATILEB;

#pragma unroll
        for (int kk = 0; kk < 4; kk++) {
            uint32_t af[2][4], bf[4][2];
#pragma unroll
            for (int mt = 0; mt < 2; mt++) {
                uint32_t off = (uint32_t)((wm * 32 + mt * 16 + (l & 15)) * 128 +
                                          (((kk * 2 + (l >> 4)) ^ (l & 7)) * 16));
                ldsm4(stA + off, af[mt]);
            }
#pragma unroll
            for (int np = 0; np < 2; np++) {
                uint32_t off = (uint32_t)((wn * 32 + np * 16 + (l & 7) + ((l >> 4) & 1) * 8) * 128 +
                                          (((kk * 2 + ((l >> 3) & 1)) ^ (l & 7)) * 16));
                uint32_t r[4];
                ldsm4(stB + off, r);
                bf[np * 2][0] = r[0];     bf[np * 2][1] = r[1];
                bf[np * 2 + 1][0] = r[2]; bf[np * 2 + 1][1] = r[3];
            }
#pragma unroll
            for (int mt = 0; mt < 2; mt++)
#pragma unroll
                for (int nt = 0; nt < 4; nt++)
                    mma_f16(acc[mt][nt], af[mt], bf[nt]);
        }
    }

    // epilogue: bias + relu -> fp16 (rows padded to NPAD, no bounds checks)
#pragma unroll
    for (int mt = 0; mt < 2; mt++) {
        int r0 = bm + wm * 32 + mt * 16 + (l >> 2);
#pragma unroll
        for (int nt = 0; nt < 4; nt++) {
            int col = bn + wn * 32 + nt * 8 + 2 * (l & 3);
            float2 bb = *(const float2*)(g_bias + col);
            __half2 o0 = __float22half2_rn(make_float2(fmaxf(acc[mt][nt][0] + bb.x, 0.f),
                                                        fmaxf(acc[mt][nt][1] + bb.y, 0.f)));
            __half2 o1 = __float22half2_rn(make_float2(fmaxf(acc[mt][nt][2] + bb.x, 0.f),
                                                        fmaxf(acc[mt][nt][3] + bb.y, 0.f)));
            *(__half2*)(g_QKVh + (size_t)r0 * NOUT + col) = o0;
            *(__half2*)(g_QKVh + (size_t)(r0 + 8) * NOUT + col) = o1;
        }
    }
}

// ---------------- attention via CSR: warp per dst, 4-edge batched gathers ----------------
__global__ void attn_csr(float* __restrict__ out) {
    int d = blockIdx.x * (blockDim.x >> 5) + (threadIdx.x >> 5);
    if (d >= MAXN) return;
    int lane = threadIdx.x & 31;
    int e0 = __ldg(g_rowptr + d), e1 = __ldg(g_rowptr + d + 1);
    uint2 qp = __ldg((const uint2*)(g_QKVh + (size_t)d * NOUT) + lane);
    float2 q0 = __half22float2(*(__half2*)&qp.x);
    float2 q1 = __half22float2(*(__half2*)&qp.y);
    float4 wv = {0, 0, 0, 0};
    float z = 0.f;

#define EDGE(kp, vp) do { \
        float2 k0 = __half22float2(*(__half2*)&(kp).x); \
        float2 k1 = __half22float2(*(__half2*)&(kp).y); \
        float p = q0.x * k0.x + q0.y * k0.y + q1.x * k1.x + q1.y * k1.y; \
        p += __shfl_xor_sync(0xffffffffu, p, 1); \
        p += __shfl_xor_sync(0xffffffffu, p, 2); \
        float wgt = __expf(fminf(fmaxf(p * 0.25f, -10.f), 10.f)); \
        float2 v0 = __half22float2(*(__half2*)&(vp).x); \
        float2 v1 = __half22float2(*(__half2*)&(vp).y); \
        wv.x += v0.x * wgt; wv.y += v0.y * wgt; \
        wv.z += v1.x * wgt; wv.w += v1.y * wgt; \
        z += wgt; } while (0)

    int e = e0;
#pragma unroll 1
    for (; e + 4 <= e1; e += 4) {
        size_t s0 = (size_t)(__ldg(g_epack + e)     >> 3) * NOUT;
        size_t s1 = (size_t)(__ldg(g_epack + e + 1) >> 3) * NOUT;
        size_t s2 = (size_t)(__ldg(g_epack + e + 2) >> 3) * NOUT;
        size_t s3 = (size_t)(__ldg(g_epack + e + 3) >> 3) * NOUT;
        uint2 k0p = __ldg((const uint2*)(g_QKVh + s0 + D) + lane);
        uint2 v0p = __ldg((const uint2*)(g_QKVh + s0 + 2 * D) + lane);
        uint2 k1p = __ldg((const uint2*)(g_QKVh + s1 + D) + lane);
        uint2 v1p = __ldg((const uint2*)(g_QKVh + s1 + 2 * D) + lane);
        uint2 k2p = __ldg((const uint2*)(g_QKVh + s2 + D) + lane);
        uint2 v2p = __ldg((const uint2*)(g_QKVh + s2 + 2 * D) + lane);
        uint2 k3p = __ldg((const uint2*)(g_QKVh + s3 + D) + lane);
        uint2 v3p = __ldg((const uint2*)(g_QKVh + s3 + 2 * D) + lane);
        EDGE(k0p, v0p);
        EDGE(k1p, v1p);
        EDGE(k2p, v2p);
        EDGE(k3p, v3p);
    }
#pragma unroll 1
    for (; e < e1; e++) {
        size_t s = (size_t)(__ldg(g_epack + e) >> 3) * NOUT;
        uint2 kp = __ldg((const uint2*)(g_QKVh + s + D) + lane);
        uint2 vp = __ldg((const uint2*)(g_QKVh + s + 2 * D) + lane);
        EDGE(kp, vp);
    }
#undef EDGE

    float inv = 1.f / (z + 1e-6f);
    float4 o = {wv.x * inv, wv.y * inv, wv.z * inv, wv.w * inv};
    *((float4*)(out + (size_t)d * D) + lane) = o;
}

extern "C" void kernel_launch(void* const* d_in, const int* in_sizes, int n_in,
                              void* d_out, int out_size) {
    const float* h   = (const float*)d_in[0];
    const int*   src = (const int*)d_in[1];
    const int*   dst = (const int*)d_in[2];
    const int*   et  = (const int*)d_in[3];
    const float* Wq_basis = (const float*)d_in[4];
    const float* Wq_coef  = (const float*)d_in[5];
    const float* bq       = (const float*)d_in[6];
    const float* Wk_basis = (const float*)d_in[7];
    const float* Wk_coef  = (const float*)d_in[8];
    const float* bk       = (const float*)d_in[9];
    const float* Wv_basis = (const float*)d_in[10];
    const float* Wv_coef  = (const float*)d_in[11];
    const float* bv       = (const float*)d_in[12];
    float* out = (float*)d_out;

    int E = in_sizes[1];       // 500000

    static bool attr_set = false;
    if (!attr_set) {
        cudaFuncSetAttribute(gemm_qkv_f16, cudaFuncAttributeMaxDynamicSharedMemorySize, SMEM_TOTAL);
        attr_set = true;
    }

    // Fork: side stream runs conv_h + build_Wt concurrently with the CSR build.
    cudaEventRecord(g_side.evFork, 0);
    cudaStreamWaitEvent(g_side.s, g_side.evFork, 0);

    conv_h<<<(MAXN * D / 4 + 255) / 256, 256, 0, g_side.s>>>(h);
    cudaEventRecord(g_side.evJoin1, g_side.s);     // conv_h done
    build_Wt<<<(NOUT * KDIM + 255) / 256, 256, 0, g_side.s>>>(Wq_basis, Wq_coef, bq,
                                                              Wk_basis, Wk_coef, bk,
                                                              Wv_basis, Wv_coef, bv);
    cudaEventRecord(g_side.evJoin2, g_side.s);     // build_Wt done

    // Main stream: CSR build
    zero_deg<<<(MAXN + 255) / 256, 256>>>();
    {
        int th = (E + 3) / 4;
        hist_deg<<<(th + 255) / 256, 256>>>(dst, E);
    }
    scan_deg<<<1, SCAN_T>>>();
    {
        int th = (E + 1) / 2;
        place_edges<<<(th + 255) / 256, 256>>>(src, dst, et, E);
    }

    // scatter needs CSR + conv_h
    cudaStreamWaitEvent(0, g_side.evJoin1, 0);
    scatter_csr<<<(MAXN * 32 + 255) / 256, 256>>>();

    // gemm needs scatter + build_Wt
    cudaStreamWaitEvent(0, g_side.evJoin2, 0);
    {
        dim3 gg(NOUT / 128, NPAD / 64);
        gemm_qkv_f16<<<gg, 256, SMEM_TOTAL>>>();
    }

    attn_csr<<<(MAXN * 32 + 255) / 256, 256>>>(out);
}